// round 6
// baseline (speedup 1.0000x reference)
#include <cuda_runtime.h>
#include <math.h>

#define N_NODES 100000
#define F_IN    500
#define HID     64
#define NCLS    40

// ---------------- scratch (static device globals; no allocation) ----------------
__device__ alignas(256) float g_deg [N_NODES];
__device__ alignas(256) float g_dinv[N_NODES];
__device__ alignas(256) float g_xw1 [(size_t)N_NODES * HID];    // x @ W1
__device__ alignas(256) float g_h   [(size_t)N_NODES * HID];    // aggregated layer-1 (pre-act)
__device__ alignas(256) float g_xw2 [(size_t)N_NODES * NCLS];   // h @ W2
__device__ alignas(256) float g_logits[(size_t)N_NODES * NCLS]; // aggregated layer-2 (pre-bias)

// ---------------- degree / normalization ----------------
__global__ void k_deg_init() {
    int i = blockIdx.x * blockDim.x + threadIdx.x;
    if (i < N_NODES) g_deg[i] = 1.0f;  // self-loop
}

__global__ void k_deg_count(const int* __restrict__ dst, int E) {
    int i = blockIdx.x * blockDim.x + threadIdx.x;
    if (i < E) {
        int d = dst[i];
        if ((unsigned)d < N_NODES) atomicAdd(&g_deg[d], 1.0f);
    }
}

__global__ void k_dinv() {
    int i = blockIdx.x * blockDim.x + threadIdx.x;
    if (i < N_NODES) g_dinv[i] = rsqrtf(g_deg[i]);  // deg >= 1 always
}

// ---------------- GEMM1: xw1 = x @ W1 ; also g_h = xw1 * dinv^2 (self-loop init) ----
// 64x64 tile, K-chunks of 50, 256 threads, 4x4 microtile per thread.
__global__ void k_gemm1(const float* __restrict__ x, const float* __restrict__ W1) {
    __shared__ float xs[64][50];
    __shared__ float ws[50][64];
    const int tid = threadIdx.x;
    const int tx = tid & 15, ty = tid >> 4;
    const int row0 = blockIdx.x * 64;

    float acc[4][4] = {};

    for (int k0 = 0; k0 < F_IN; k0 += 50) {
        #pragma unroll
        for (int i = 0; i < 13; i++) {
            int idx = tid + i * 256;
            if (idx < 3200) {
                int r = idx / 50, c = idx - r * 50;
                int gr = row0 + r;
                xs[r][c] = (gr < N_NODES) ? x[(size_t)gr * F_IN + k0 + c] : 0.0f;
                int r2 = idx >> 6, c2 = idx & 63;
                ws[r2][c2] = W1[(size_t)(k0 + r2) * HID + c2];
            }
        }
        __syncthreads();

        #pragma unroll
        for (int kk = 0; kk < 50; kk++) {
            float4 b = *(const float4*)&ws[kk][tx * 4];
            float a0 = xs[ty * 4 + 0][kk];
            float a1 = xs[ty * 4 + 1][kk];
            float a2 = xs[ty * 4 + 2][kk];
            float a3 = xs[ty * 4 + 3][kk];
            acc[0][0] += a0 * b.x; acc[0][1] += a0 * b.y; acc[0][2] += a0 * b.z; acc[0][3] += a0 * b.w;
            acc[1][0] += a1 * b.x; acc[1][1] += a1 * b.y; acc[1][2] += a1 * b.z; acc[1][3] += a1 * b.w;
            acc[2][0] += a2 * b.x; acc[2][1] += a2 * b.y; acc[2][2] += a2 * b.z; acc[2][3] += a2 * b.w;
            acc[3][0] += a3 * b.x; acc[3][1] += a3 * b.y; acc[3][2] += a3 * b.z; acc[3][3] += a3 * b.w;
        }
        __syncthreads();
    }

    #pragma unroll
    for (int i = 0; i < 4; i++) {
        int gr = row0 + ty * 4 + i;
        if (gr < N_NODES) {
            float di = g_dinv[gr];
            float d2 = di * di;
            float4 v = make_float4(acc[i][0], acc[i][1], acc[i][2], acc[i][3]);
            *(float4*)&g_xw1[(size_t)gr * HID + tx * 4] = v;
            float4 s = make_float4(v.x * d2, v.y * d2, v.z * d2, v.w * d2);
            *(float4*)&g_h[(size_t)gr * HID + tx * 4] = s;
        }
    }
}

// ---------------- edge aggregation, layer 1: g_h[dst] += xw1[src]*norm -------------
// 16 threads per edge, float4 chunks, scalar atomicAdd (ptxas emits REDG — no return).
__global__ void k_agg1(const int* __restrict__ src,
                       const int* __restrict__ dst, long long nwork) {
    long long idx = (long long)blockIdx.x * blockDim.x + threadIdx.x;
    if (idx >= nwork) return;
    long long e = idx >> 4;
    int c = (int)(idx & 15) << 2;
    int s = src[e];
    int d = dst[e];
    if ((unsigned)s >= N_NODES || (unsigned)d >= N_NODES) return;
    float nrm = g_dinv[s] * g_dinv[d];
    float4 v = *(const float4*)&g_xw1[(size_t)s * HID + c];
    float* p = &g_h[(size_t)d * HID + c];
    atomicAdd(p + 0, v.x * nrm);
    atomicAdd(p + 1, v.y * nrm);
    atomicAdd(p + 2, v.z * nrm);
    atomicAdd(p + 3, v.w * nrm);
}

// ---------------- GEMM2: xw2 = relu(g_h + b1) @ W2 ; g_logits = xw2 * dinv^2 -------
__global__ void k_gemm2(const float* __restrict__ W2, const float* __restrict__ b1) {
    __shared__ float ws[HID * NCLS];
    __shared__ float bs[HID];
    int tid = threadIdx.x;
    for (int i = tid; i < HID * NCLS; i += 256) ws[i] = W2[i];
    if (tid < HID) bs[tid] = b1[tid];
    __syncthreads();

    int row = blockIdx.x * 256 + tid;
    if (row >= N_NODES) return;

    float a[HID];
    const float4* hp = (const float4*)&g_h[(size_t)row * HID];
    #pragma unroll
    for (int i = 0; i < HID / 4; i++) {
        float4 v = hp[i];
        a[i * 4 + 0] = fmaxf(v.x + bs[i * 4 + 0], 0.0f);
        a[i * 4 + 1] = fmaxf(v.y + bs[i * 4 + 1], 0.0f);
        a[i * 4 + 2] = fmaxf(v.z + bs[i * 4 + 2], 0.0f);
        a[i * 4 + 3] = fmaxf(v.w + bs[i * 4 + 3], 0.0f);
    }

    float acc[NCLS] = {};
    #pragma unroll 8
    for (int k = 0; k < HID; k++) {
        float ak = a[k];
        #pragma unroll
        for (int j = 0; j < NCLS; j += 4) {
            float4 w = *(const float4*)&ws[k * NCLS + j];
            acc[j + 0] += ak * w.x;
            acc[j + 1] += ak * w.y;
            acc[j + 2] += ak * w.z;
            acc[j + 3] += ak * w.w;
        }
    }

    float di = g_dinv[row];
    float d2 = di * di;
    float4* xo = (float4*)&g_xw2[(size_t)row * NCLS];
    float4* lo = (float4*)&g_logits[(size_t)row * NCLS];
    #pragma unroll
    for (int j = 0; j < NCLS / 4; j++) {
        float4 v = make_float4(acc[j * 4 + 0], acc[j * 4 + 1], acc[j * 4 + 2], acc[j * 4 + 3]);
        xo[j] = v;
        lo[j] = make_float4(v.x * d2, v.y * d2, v.z * d2, v.w * d2);
    }
}

// ---------------- edge aggregation, layer 2: g_logits[dst] += xw2[src]*norm --------
__global__ void k_agg2(const int* __restrict__ src,
                       const int* __restrict__ dst, long long nwork) {
    long long idx = (long long)blockIdx.x * blockDim.x + threadIdx.x;
    if (idx >= nwork) return;
    long long e = idx / 10;
    int c = (int)(idx - e * 10) * 4;
    int s = src[e];
    int d = dst[e];
    if ((unsigned)s >= N_NODES || (unsigned)d >= N_NODES) return;
    float nrm = g_dinv[s] * g_dinv[d];
    float4 v = *(const float4*)&g_xw2[(size_t)s * NCLS + c];
    float* p = &g_logits[(size_t)d * NCLS + c];
    atomicAdd(p + 0, v.x * nrm);
    atomicAdd(p + 1, v.y * nrm);
    atomicAdd(p + 2, v.z * nrm);
    atomicAdd(p + 3, v.w * nrm);
}

// ---------------- finalize: add b2, log_softmax, write both outputs ----------------
__global__ void k_final(const float* __restrict__ b2,
                        float* __restrict__ out_lsm,
                        float* __restrict__ out_logit) {
    int row = blockIdx.x * blockDim.x + threadIdx.x;
    if (row >= N_NODES) return;

    float v[NCLS];
    const float4* lp = (const float4*)&g_logits[(size_t)row * NCLS];
    #pragma unroll
    for (int i = 0; i < NCLS / 4; i++) {
        float4 t = lp[i];
        v[i * 4 + 0] = t.x + b2[i * 4 + 0];
        v[i * 4 + 1] = t.y + b2[i * 4 + 1];
        v[i * 4 + 2] = t.z + b2[i * 4 + 2];
        v[i * 4 + 3] = t.w + b2[i * 4 + 3];
    }

    float m = -1e30f;
    #pragma unroll
    for (int j = 0; j < NCLS; j++) m = fmaxf(m, v[j]);
    float ssum = 0.0f;
    #pragma unroll
    for (int j = 0; j < NCLS; j++) ssum += expf(v[j] - m);
    float lse = m + logf(ssum);

    #pragma unroll
    for (int j = 0; j < NCLS; j++) {
        if (out_logit) out_logit[(size_t)row * NCLS + j] = v[j];
        out_lsm[(size_t)row * NCLS + j] = v[j] - lse;
    }
}

// ---------------- launch ----------------
extern "C" void kernel_launch(void* const* d_in, const int* in_sizes, int n_in,
                              void* d_out, int out_size) {
    const float* x   = (const float*)d_in[0];
    const int*   ei  = (const int*)d_in[1];   // edge_index: JAX downcasts int64->int32
    const float* W1  = (const float*)d_in[2];
    const float* b1  = (const float*)d_in[3];
    const float* W2  = (const float*)d_in[4];
    const float* b2  = (const float*)d_in[5];

    const int E = in_sizes[1] / 2;
    const int* srcp = ei;
    const int* dstp = ei + E;

    float* out = (float*)d_out;
    float* out_lsm = out;
    float* out_logit = nullptr;
    if (out_size >= 2 * N_NODES * NCLS) {
        out_logit = out + (size_t)N_NODES * NCLS;
    }

    const int T = 256;
    const int nodeBlocks = (N_NODES + T - 1) / T;

    k_deg_init <<<nodeBlocks, T>>>();
    k_deg_count<<<(E + T - 1) / T, T>>>(dstp, E);
    k_dinv     <<<nodeBlocks, T>>>();

    k_gemm1<<<(N_NODES + 63) / 64, 256>>>(x, W1);

    long long w1 = (long long)E * 16;
    k_agg1<<<(int)((w1 + T - 1) / T), T>>>(srcp, dstp, w1);

    k_gemm2<<<nodeBlocks, T>>>(W2, b1);

    long long w2 = (long long)E * 10;
    k_agg2<<<(int)((w2 + T - 1) / T), T>>>(srcp, dstp, w2);

    k_final<<<nodeBlocks, T>>>(b2, out_lsm, out_logit);
}

// round 8
// speedup vs baseline: 1.3673x; 1.3673x over previous
#include <cuda_runtime.h>
#include <math.h>

#define N_NODES 100000
#define F_IN    500
#define HID     64
#define NCLS    40
#define E_MAX   2000000

// ---------------- scratch (static device globals; no allocation) ----------------
__device__ alignas(256) float g_deg [N_NODES];
__device__ alignas(256) float g_dinv[N_NODES];
__device__ alignas(256) float g_norm[E_MAX];
__device__ alignas(256) float g_xw1 [(size_t)N_NODES * HID];    // x @ W1
__device__ alignas(256) float g_h   [(size_t)N_NODES * HID];    // aggregated layer-1 (pre-act)
__device__ alignas(256) float g_xw2 [(size_t)N_NODES * NCLS];   // h @ W2
__device__ alignas(256) float g_logits[(size_t)N_NODES * NCLS]; // aggregated layer-2 (pre-bias)

// ---------------- degree / normalization ----------------
__global__ void k_deg_init() {
    int i = blockIdx.x * blockDim.x + threadIdx.x;
    if (i < N_NODES) g_deg[i] = 1.0f;  // self-loop
}

__global__ void k_deg_count(const int* __restrict__ dst, int E) {
    int i = blockIdx.x * blockDim.x + threadIdx.x;
    if (i < E) {
        int d = dst[i];
        if ((unsigned)d < N_NODES) atomicAdd(&g_deg[d], 1.0f);
    }
}

__global__ void k_dinv() {
    int i = blockIdx.x * blockDim.x + threadIdx.x;
    if (i < N_NODES) g_dinv[i] = rsqrtf(g_deg[i]);  // deg >= 1 always
}

// per-edge norm = dinv[src]*dinv[dst], computed once
__global__ void k_norm(const int* __restrict__ src, const int* __restrict__ dst, int E) {
    int i = blockIdx.x * blockDim.x + threadIdx.x;
    if (i < E) {
        int s = src[i], d = dst[i];
        float v = 0.0f;
        if ((unsigned)s < N_NODES && (unsigned)d < N_NODES)
            v = g_dinv[s] * g_dinv[d];
        g_norm[i] = v;
    }
}

// ---------------- GEMM1: xw1 = x @ W1 ; g_h = xw1 * dinv^2 (self-loop init) --------
// 128x64 tile, K-chunks of 32, 256 threads, 8x4 microtile.
// A stored transposed in smem (stride 132 keeps LDS.128 aligned, STS <=4-way conflict).
#define BM 128
#define BK 32
#define XS_STRIDE 132
__global__ void k_gemm1(const float* __restrict__ x, const float* __restrict__ W1) {
    __shared__ float xs[BK * XS_STRIDE];  // xs[c*132 + r] (transposed)
    __shared__ float ws[BK * HID];        // ws[r*64 + c]
    const int tid = threadIdx.x;
    const int tx = tid & 15;   // N: 4-col group (0..15) -> cols tx*4..tx*4+3
    const int ty = tid >> 4;   // M: 8-row group (0..15) -> rows ty*8..ty*8+7
    const int row0 = blockIdx.x * BM;

    const int lc4 = tid & 7;   // xs loader: float4-col within chunk (0..7)
    const int lr  = tid >> 3;  // xs loader: row base (0..31)
    const int wc4 = tid & 15;  // ws loader: float4-col (0..15)
    const int wr  = tid >> 4;  // ws loader: row base (0..15)

    float acc[8][4] = {};

    for (int k0 = 0; k0 < F_IN; k0 += BK) {
        // ---- load x tile (128 rows x 32 cols), transposed into xs ----
        #pragma unroll
        for (int i = 0; i < 4; i++) {
            int r  = lr + 32 * i;
            int gr = row0 + r;
            int gc = k0 + lc4 * 4;
            float4 v = make_float4(0.f, 0.f, 0.f, 0.f);
            if (gr < N_NODES) {
                if (gc + 3 < F_IN) {
                    v = *(const float4*)&x[(size_t)gr * F_IN + gc];
                } else {
                    float t0 = (gc + 0 < F_IN) ? x[(size_t)gr * F_IN + gc + 0] : 0.f;
                    float t1 = (gc + 1 < F_IN) ? x[(size_t)gr * F_IN + gc + 1] : 0.f;
                    float t2 = (gc + 2 < F_IN) ? x[(size_t)gr * F_IN + gc + 2] : 0.f;
                    float t3 = (gc + 3 < F_IN) ? x[(size_t)gr * F_IN + gc + 3] : 0.f;
                    v = make_float4(t0, t1, t2, t3);
                }
            }
            xs[(lc4 * 4 + 0) * XS_STRIDE + r] = v.x;
            xs[(lc4 * 4 + 1) * XS_STRIDE + r] = v.y;
            xs[(lc4 * 4 + 2) * XS_STRIDE + r] = v.z;
            xs[(lc4 * 4 + 3) * XS_STRIDE + r] = v.w;
        }
        // ---- load W1 tile (32 rows x 64 cols) ----
        #pragma unroll
        for (int i = 0; i < 2; i++) {
            int r  = wr + 16 * i;
            int gk = k0 + r;
            float4 v = make_float4(0.f, 0.f, 0.f, 0.f);
            if (gk < F_IN) v = *(const float4*)&W1[(size_t)gk * HID + wc4 * 4];
            *(float4*)&ws[r * HID + wc4 * 4] = v;
        }
        __syncthreads();

        #pragma unroll
        for (int kk = 0; kk < BK; kk++) {
            float4 b  = *(const float4*)&ws[kk * HID + tx * 4];
            float4 a0 = *(const float4*)&xs[kk * XS_STRIDE + ty * 8];
            float4 a1 = *(const float4*)&xs[kk * XS_STRIDE + ty * 8 + 4];
            float a[8] = {a0.x, a0.y, a0.z, a0.w, a1.x, a1.y, a1.z, a1.w};
            #pragma unroll
            for (int i = 0; i < 8; i++) {
                acc[i][0] += a[i] * b.x;
                acc[i][1] += a[i] * b.y;
                acc[i][2] += a[i] * b.z;
                acc[i][3] += a[i] * b.w;
            }
        }
        __syncthreads();
    }

    #pragma unroll
    for (int i = 0; i < 8; i++) {
        int gr = row0 + ty * 8 + i;
        if (gr < N_NODES) {
            float di = g_dinv[gr];
            float d2 = di * di;
            float4 v = make_float4(acc[i][0], acc[i][1], acc[i][2], acc[i][3]);
            *(float4*)&g_xw1[(size_t)gr * HID + tx * 4] = v;
            *(float4*)&g_h  [(size_t)gr * HID + tx * 4] =
                make_float4(v.x * d2, v.y * d2, v.z * d2, v.w * d2);
        }
    }
}

// ---------------- edge aggregation, layer 1: g_h[dst] += xw1[src]*norm -------------
// 16 threads per edge, one RED.128 each.
__global__ void k_agg1(const int* __restrict__ src,
                       const int* __restrict__ dst, long long nwork) {
    long long idx = (long long)blockIdx.x * blockDim.x + threadIdx.x;
    if (idx >= nwork) return;
    long long e = idx >> 4;
    int c = (int)(idx & 15) << 2;
    int s = src[e];
    int d = dst[e];
    if ((unsigned)s >= N_NODES || (unsigned)d >= N_NODES) return;
    float nrm = g_norm[e];
    float4 v = *(const float4*)&g_xw1[(size_t)s * HID + c];
    float* p = &g_h[(size_t)d * HID + c];
    asm volatile("red.global.add.v4.f32 [%0], {%1,%2,%3,%4};"
                 :: "l"(p), "f"(v.x * nrm), "f"(v.y * nrm), "f"(v.z * nrm), "f"(v.w * nrm)
                 : "memory");
}

// ---------------- GEMM2: xw2 = relu(g_h + b1) @ W2 ; g_logits = xw2 * dinv^2 -------
__global__ void k_gemm2(const float* __restrict__ W2, const float* __restrict__ b1) {
    __shared__ float ws[HID * NCLS];
    __shared__ float bs[HID];
    int tid = threadIdx.x;
    for (int i = tid; i < HID * NCLS; i += 256) ws[i] = W2[i];
    if (tid < HID) bs[tid] = b1[tid];
    __syncthreads();

    int row = blockIdx.x * 256 + tid;
    if (row >= N_NODES) return;

    float a[HID];
    const float4* hp = (const float4*)&g_h[(size_t)row * HID];
    #pragma unroll
    for (int i = 0; i < HID / 4; i++) {
        float4 v = hp[i];
        a[i * 4 + 0] = fmaxf(v.x + bs[i * 4 + 0], 0.0f);
        a[i * 4 + 1] = fmaxf(v.y + bs[i * 4 + 1], 0.0f);
        a[i * 4 + 2] = fmaxf(v.z + bs[i * 4 + 2], 0.0f);
        a[i * 4 + 3] = fmaxf(v.w + bs[i * 4 + 3], 0.0f);
    }

    float acc[NCLS] = {};
    #pragma unroll 8
    for (int k = 0; k < HID; k++) {
        float ak = a[k];
        #pragma unroll
        for (int j = 0; j < NCLS; j += 4) {
            float4 w = *(const float4*)&ws[k * NCLS + j];
            acc[j + 0] += ak * w.x;
            acc[j + 1] += ak * w.y;
            acc[j + 2] += ak * w.z;
            acc[j + 3] += ak * w.w;
        }
    }

    float di = g_dinv[row];
    float d2 = di * di;
    float4* xo = (float4*)&g_xw2[(size_t)row * NCLS];
    float4* lo = (float4*)&g_logits[(size_t)row * NCLS];
    #pragma unroll
    for (int j = 0; j < NCLS / 4; j++) {
        float4 v = make_float4(acc[j * 4 + 0], acc[j * 4 + 1], acc[j * 4 + 2], acc[j * 4 + 3]);
        xo[j] = v;
        lo[j] = make_float4(v.x * d2, v.y * d2, v.z * d2, v.w * d2);
    }
}

// ---------------- edge aggregation, layer 2: g_logits[dst] += xw2[src]*norm --------
__global__ void k_agg2(const int* __restrict__ src,
                       const int* __restrict__ dst, long long nwork) {
    long long idx = (long long)blockIdx.x * blockDim.x + threadIdx.x;
    if (idx >= nwork) return;
    long long e = idx / 10;
    int c = (int)(idx - e * 10) * 4;
    int s = src[e];
    int d = dst[e];
    if ((unsigned)s >= N_NODES || (unsigned)d >= N_NODES) return;
    float nrm = g_norm[e];
    float4 v = *(const float4*)&g_xw2[(size_t)s * NCLS + c];
    float* p = &g_logits[(size_t)d * NCLS + c];
    asm volatile("red.global.add.v4.f32 [%0], {%1,%2,%3,%4};"
                 :: "l"(p), "f"(v.x * nrm), "f"(v.y * nrm), "f"(v.z * nrm), "f"(v.w * nrm)
                 : "memory");
}

// ---------------- finalize: add b2, log_softmax, write both outputs ----------------
__global__ void k_final(const float* __restrict__ b2,
                        float* __restrict__ out_lsm,
                        float* __restrict__ out_logit) {
    int row = blockIdx.x * blockDim.x + threadIdx.x;
    if (row >= N_NODES) return;

    float v[NCLS];
    const float4* lp = (const float4*)&g_logits[(size_t)row * NCLS];
    #pragma unroll
    for (int i = 0; i < NCLS / 4; i++) {
        float4 t = lp[i];
        v[i * 4 + 0] = t.x + b2[i * 4 + 0];
        v[i * 4 + 1] = t.y + b2[i * 4 + 1];
        v[i * 4 + 2] = t.z + b2[i * 4 + 2];
        v[i * 4 + 3] = t.w + b2[i * 4 + 3];
    }

    float m = -1e30f;
    #pragma unroll
    for (int j = 0; j < NCLS; j++) m = fmaxf(m, v[j]);
    float ssum = 0.0f;
    #pragma unroll
    for (int j = 0; j < NCLS; j++) ssum += expf(v[j] - m);
    float lse = m + logf(ssum);

    #pragma unroll
    for (int j = 0; j < NCLS; j++) {
        if (out_logit) out_logit[(size_t)row * NCLS + j] = v[j];
        out_lsm[(size_t)row * NCLS + j] = v[j] - lse;
    }
}

// ---------------- launch ----------------
extern "C" void kernel_launch(void* const* d_in, const int* in_sizes, int n_in,
                              void* d_out, int out_size) {
    const float* x   = (const float*)d_in[0];
    const int*   ei  = (const int*)d_in[1];   // edge_index is int32 (JAX x64 disabled)
    const float* W1  = (const float*)d_in[2];
    const float* b1  = (const float*)d_in[3];
    const float* W2  = (const float*)d_in[4];
    const float* b2  = (const float*)d_in[5];

    const int E = in_sizes[1] / 2;
    const int* srcp = ei;
    const int* dstp = ei + E;

    float* out = (float*)d_out;
    float* out_lsm = out;
    float* out_logit = nullptr;
    if (out_size >= 2 * N_NODES * NCLS) {
        out_logit = out + (size_t)N_NODES * NCLS;
    }

    const int T = 256;
    const int nodeBlocks = (N_NODES + T - 1) / T;
    const int edgeBlocks = (E + T - 1) / T;

    k_deg_init <<<nodeBlocks, T>>>();
    k_deg_count<<<edgeBlocks, T>>>(dstp, E);
    k_dinv     <<<nodeBlocks, T>>>();
    k_norm     <<<edgeBlocks, T>>>(srcp, dstp, E);

    k_gemm1<<<(N_NODES + BM - 1) / BM, 256>>>(x, W1);

    long long w1 = (long long)E * 16;
    k_agg1<<<(int)((w1 + T - 1) / T), T>>>(srcp, dstp, w1);

    k_gemm2<<<nodeBlocks, T>>>(W2, b1);

    long long w2 = (long long)E * 10;
    k_agg2<<<(int)((w2 + T - 1) / T), T>>>(srcp, dstp, w2);

    k_final<<<nodeBlocks, T>>>(b2, out_lsm, out_logit);
}

// round 9
// speedup vs baseline: 1.6580x; 1.2126x over previous
#include <cuda_runtime.h>
#include <math.h>

#define N_NODES 100000
#define F_IN    500
#define HID     64
#define NCLS    40
#define E_MAX   2000000
#define SCAN_NB ((N_NODES + 255) / 256)   // 391

// ---------------- scratch (static device globals; no allocation) ----------------
__device__ alignas(256) float g_dinv[N_NODES];
__device__ alignas(256) int   g_cnt   [N_NODES];     // in-degree (excl self-loop)
__device__ alignas(256) int   g_rowptr[N_NODES];
__device__ alignas(256) int   g_cursor[N_NODES];
__device__ alignas(256) int   g_bsum  [512];
__device__ alignas(16)  int2  g_csr   [E_MAX];       // {src, __float_as_int(norm)}
__device__ alignas(256) float g_xw1 [(size_t)N_NODES * HID];
__device__ alignas(256) float g_h   [(size_t)N_NODES * HID];
__device__ alignas(256) float g_xw2 [(size_t)N_NODES * NCLS];
__device__ alignas(256) float g_logits[(size_t)N_NODES * NCLS];

// ---------------- degree / csr build ----------------
__global__ void k_zero() {
    int i = blockIdx.x * blockDim.x + threadIdx.x;
    if (i < N_NODES) { g_cnt[i] = 0; g_cursor[i] = 0; }
}

__global__ void k_count(const int* __restrict__ dst, int E) {
    int i = blockIdx.x * blockDim.x + threadIdx.x;
    if (i < E) {
        int d = dst[i];
        if ((unsigned)d < N_NODES) atomicAdd(&g_cnt[d], 1);
    }
}

__global__ void k_dinv() {
    int i = blockIdx.x * blockDim.x + threadIdx.x;
    if (i < N_NODES) g_dinv[i] = rsqrtf((float)(g_cnt[i] + 1));  // +1 self-loop
}

// block-local exclusive scan of g_cnt -> g_rowptr (partial), block totals -> g_bsum
__global__ void k_scan_local() {
    __shared__ int sh[256];
    int tid = threadIdx.x;
    int i = blockIdx.x * 256 + tid;
    int v = (i < N_NODES) ? g_cnt[i] : 0;
    sh[tid] = v;
    __syncthreads();
    #pragma unroll
    for (int off = 1; off < 256; off <<= 1) {
        int t = (tid >= off) ? sh[tid - off] : 0;
        __syncthreads();
        sh[tid] += t;
        __syncthreads();
    }
    if (i < N_NODES) g_rowptr[i] = sh[tid] - v;   // exclusive within block
    if (tid == 255) g_bsum[blockIdx.x] = sh[255];
}

// single-block exclusive scan of the 391 block sums
__global__ void k_scan_bsum() {
    __shared__ int sh[512];
    int tid = threadIdx.x;
    int v = (tid < SCAN_NB) ? g_bsum[tid] : 0;
    sh[tid] = v;
    __syncthreads();
    #pragma unroll
    for (int off = 1; off < 512; off <<= 1) {
        int t = (tid >= off) ? sh[tid - off] : 0;
        __syncthreads();
        sh[tid] += t;
        __syncthreads();
    }
    if (tid < SCAN_NB) g_bsum[tid] = sh[tid] - v;  // exclusive
}

__global__ void k_scan_add() {
    int i = blockIdx.x * 256 + threadIdx.x;
    if (i < N_NODES) g_rowptr[i] += g_bsum[blockIdx.x];
}

// scatter edges into CSR (by dst), packing {src, norm}
__global__ void k_fill(const int* __restrict__ src, const int* __restrict__ dst, int E) {
    int i = blockIdx.x * blockDim.x + threadIdx.x;
    if (i >= E) return;
    int s = src[i], d = dst[i];
    if ((unsigned)s >= N_NODES || (unsigned)d >= N_NODES) return;
    float nrm = g_dinv[s] * g_dinv[d];
    int pos = g_rowptr[d] + atomicAdd(&g_cursor[d], 1);
    g_csr[pos] = make_int2(s, __float_as_int(nrm));
}

// ---------------- GEMM1: xw1 = x @ W1 ; g_h = xw1 * dinv^2 (self-loop term) --------
#define BM 128
#define BK 32
#define XS_STRIDE 132
__global__ void k_gemm1(const float* __restrict__ x, const float* __restrict__ W1) {
    __shared__ float xs[BK * XS_STRIDE];  // transposed: xs[c*132 + r]
    __shared__ float ws[BK * HID];
    const int tid = threadIdx.x;
    const int tx = tid & 15;
    const int ty = tid >> 4;
    const int row0 = blockIdx.x * BM;

    const int lc4 = tid & 7;
    const int lr  = tid >> 3;
    const int wc4 = tid & 15;
    const int wr  = tid >> 4;

    float acc[8][4] = {};

    for (int k0 = 0; k0 < F_IN; k0 += BK) {
        #pragma unroll
        for (int i = 0; i < 4; i++) {
            int r  = lr + 32 * i;
            int gr = row0 + r;
            int gc = k0 + lc4 * 4;
            float4 v = make_float4(0.f, 0.f, 0.f, 0.f);
            if (gr < N_NODES) {
                if (gc + 3 < F_IN) {
                    v = *(const float4*)&x[(size_t)gr * F_IN + gc];
                } else {
                    float t0 = (gc + 0 < F_IN) ? x[(size_t)gr * F_IN + gc + 0] : 0.f;
                    float t1 = (gc + 1 < F_IN) ? x[(size_t)gr * F_IN + gc + 1] : 0.f;
                    float t2 = (gc + 2 < F_IN) ? x[(size_t)gr * F_IN + gc + 2] : 0.f;
                    float t3 = (gc + 3 < F_IN) ? x[(size_t)gr * F_IN + gc + 3] : 0.f;
                    v = make_float4(t0, t1, t2, t3);
                }
            }
            xs[(lc4 * 4 + 0) * XS_STRIDE + r] = v.x;
            xs[(lc4 * 4 + 1) * XS_STRIDE + r] = v.y;
            xs[(lc4 * 4 + 2) * XS_STRIDE + r] = v.z;
            xs[(lc4 * 4 + 3) * XS_STRIDE + r] = v.w;
        }
        #pragma unroll
        for (int i = 0; i < 2; i++) {
            int r  = wr + 16 * i;
            int gk = k0 + r;
            float4 v = make_float4(0.f, 0.f, 0.f, 0.f);
            if (gk < F_IN) v = *(const float4*)&W1[(size_t)gk * HID + wc4 * 4];
            *(float4*)&ws[r * HID + wc4 * 4] = v;
        }
        __syncthreads();

        #pragma unroll
        for (int kk = 0; kk < BK; kk++) {
            float4 b  = *(const float4*)&ws[kk * HID + tx * 4];
            float4 a0 = *(const float4*)&xs[kk * XS_STRIDE + ty * 8];
            float4 a1 = *(const float4*)&xs[kk * XS_STRIDE + ty * 8 + 4];
            float a[8] = {a0.x, a0.y, a0.z, a0.w, a1.x, a1.y, a1.z, a1.w};
            #pragma unroll
            for (int i = 0; i < 8; i++) {
                acc[i][0] += a[i] * b.x;
                acc[i][1] += a[i] * b.y;
                acc[i][2] += a[i] * b.z;
                acc[i][3] += a[i] * b.w;
            }
        }
        __syncthreads();
    }

    #pragma unroll
    for (int i = 0; i < 8; i++) {
        int gr = row0 + ty * 8 + i;
        if (gr < N_NODES) {
            float di = g_dinv[gr];
            float d2 = di * di;
            float4 v = make_float4(acc[i][0], acc[i][1], acc[i][2], acc[i][3]);
            *(float4*)&g_xw1[(size_t)gr * HID + tx * 4] = v;
            *(float4*)&g_h  [(size_t)gr * HID + tx * 4] =
                make_float4(v.x * d2, v.y * d2, v.z * d2, v.w * d2);
        }
    }
}

// ---------------- CSR aggregation, layer 1: g_h[d] = self + sum_e xw1[s]*norm -------
// 16 threads per node, one float4 column-chunk each; gather-only, no atomics.
__global__ void k_agg1(long long nwork) {
    long long idx = (long long)blockIdx.x * blockDim.x + threadIdx.x;
    if (idx >= nwork) return;
    int node = (int)(idx >> 4);
    int c = (int)(idx & 15) << 2;

    int beg = g_rowptr[node];
    int n   = g_cursor[node];   // final filled count

    float* hp = &g_h[(size_t)node * HID + c];
    float4 acc = *(const float4*)hp;   // self-loop term from gemm1 epilogue

    int j = 0;
    for (; j + 1 < n; j += 2) {
        int2 e0 = g_csr[beg + j];
        int2 e1 = g_csr[beg + j + 1];
        float4 v0 = *(const float4*)&g_xw1[(size_t)e0.x * HID + c];
        float4 v1 = *(const float4*)&g_xw1[(size_t)e1.x * HID + c];
        float n0 = __int_as_float(e0.y);
        float n1 = __int_as_float(e1.y);
        acc.x += v0.x * n0 + v1.x * n1;
        acc.y += v0.y * n0 + v1.y * n1;
        acc.z += v0.z * n0 + v1.z * n1;
        acc.w += v0.w * n0 + v1.w * n1;
    }
    if (j < n) {
        int2 e0 = g_csr[beg + j];
        float4 v0 = *(const float4*)&g_xw1[(size_t)e0.x * HID + c];
        float n0 = __int_as_float(e0.y);
        acc.x += v0.x * n0;
        acc.y += v0.y * n0;
        acc.z += v0.z * n0;
        acc.w += v0.w * n0;
    }
    *(float4*)hp = acc;
}

// ---------------- GEMM2: xw2 = relu(g_h + b1) @ W2 ; g_logits = xw2 * dinv^2 -------
__global__ void k_gemm2(const float* __restrict__ W2, const float* __restrict__ b1) {
    __shared__ float ws[HID * NCLS];
    __shared__ float bs[HID];
    int tid = threadIdx.x;
    for (int i = tid; i < HID * NCLS; i += 256) ws[i] = W2[i];
    if (tid < HID) bs[tid] = b1[tid];
    __syncthreads();

    int row = blockIdx.x * 256 + tid;
    if (row >= N_NODES) return;

    float a[HID];
    const float4* hp = (const float4*)&g_h[(size_t)row * HID];
    #pragma unroll
    for (int i = 0; i < HID / 4; i++) {
        float4 v = hp[i];
        a[i * 4 + 0] = fmaxf(v.x + bs[i * 4 + 0], 0.0f);
        a[i * 4 + 1] = fmaxf(v.y + bs[i * 4 + 1], 0.0f);
        a[i * 4 + 2] = fmaxf(v.z + bs[i * 4 + 2], 0.0f);
        a[i * 4 + 3] = fmaxf(v.w + bs[i * 4 + 3], 0.0f);
    }

    float acc[NCLS] = {};
    #pragma unroll 8
    for (int k = 0; k < HID; k++) {
        float ak = a[k];
        #pragma unroll
        for (int j = 0; j < NCLS; j += 4) {
            float4 w = *(const float4*)&ws[k * NCLS + j];
            acc[j + 0] += ak * w.x;
            acc[j + 1] += ak * w.y;
            acc[j + 2] += ak * w.z;
            acc[j + 3] += ak * w.w;
        }
    }

    float di = g_dinv[row];
    float d2 = di * di;
    float4* xo = (float4*)&g_xw2[(size_t)row * NCLS];
    float4* lo = (float4*)&g_logits[(size_t)row * NCLS];
    #pragma unroll
    for (int j = 0; j < NCLS / 4; j++) {
        float4 v = make_float4(acc[j * 4 + 0], acc[j * 4 + 1], acc[j * 4 + 2], acc[j * 4 + 3]);
        xo[j] = v;
        lo[j] = make_float4(v.x * d2, v.y * d2, v.z * d2, v.w * d2);
    }
}

// ---------------- CSR aggregation, layer 2: g_logits[d] = self + sum xw2[s]*norm ----
// 10 threads per node (NCLS/4 chunks).
__global__ void k_agg2(long long nwork) {
    long long idx = (long long)blockIdx.x * blockDim.x + threadIdx.x;
    if (idx >= nwork) return;
    int node = (int)(idx / 10);
    int c = (int)(idx - (long long)node * 10) * 4;

    int beg = g_rowptr[node];
    int n   = g_cursor[node];

    float* lp = &g_logits[(size_t)node * NCLS + c];
    float4 acc = *(const float4*)lp;   // self-loop term from gemm2 epilogue

    int j = 0;
    for (; j + 1 < n; j += 2) {
        int2 e0 = g_csr[beg + j];
        int2 e1 = g_csr[beg + j + 1];
        float4 v0 = *(const float4*)&g_xw2[(size_t)e0.x * NCLS + c];
        float4 v1 = *(const float4*)&g_xw2[(size_t)e1.x * NCLS + c];
        float n0 = __int_as_float(e0.y);
        float n1 = __int_as_float(e1.y);
        acc.x += v0.x * n0 + v1.x * n1;
        acc.y += v0.y * n0 + v1.y * n1;
        acc.z += v0.z * n0 + v1.z * n1;
        acc.w += v0.w * n0 + v1.w * n1;
    }
    if (j < n) {
        int2 e0 = g_csr[beg + j];
        float4 v0 = *(const float4*)&g_xw2[(size_t)e0.x * NCLS + c];
        float n0 = __int_as_float(e0.y);
        acc.x += v0.x * n0;
        acc.y += v0.y * n0;
        acc.z += v0.z * n0;
        acc.w += v0.w * n0;
    }
    *(float4*)lp = acc;
}

// ---------------- finalize: add b2, log_softmax, write both outputs ----------------
__global__ void k_final(const float* __restrict__ b2,
                        float* __restrict__ out_lsm,
                        float* __restrict__ out_logit) {
    int row = blockIdx.x * blockDim.x + threadIdx.x;
    if (row >= N_NODES) return;

    float v[NCLS];
    const float4* lp = (const float4*)&g_logits[(size_t)row * NCLS];
    #pragma unroll
    for (int i = 0; i < NCLS / 4; i++) {
        float4 t = lp[i];
        v[i * 4 + 0] = t.x + b2[i * 4 + 0];
        v[i * 4 + 1] = t.y + b2[i * 4 + 1];
        v[i * 4 + 2] = t.z + b2[i * 4 + 2];
        v[i * 4 + 3] = t.w + b2[i * 4 + 3];
    }

    float m = -1e30f;
    #pragma unroll
    for (int j = 0; j < NCLS; j++) m = fmaxf(m, v[j]);
    float ssum = 0.0f;
    #pragma unroll
    for (int j = 0; j < NCLS; j++) ssum += expf(v[j] - m);
    float lse = m + logf(ssum);

    #pragma unroll
    for (int j = 0; j < NCLS; j++) {
        if (out_logit) out_logit[(size_t)row * NCLS + j] = v[j];
        out_lsm[(size_t)row * NCLS + j] = v[j] - lse;
    }
}

// ---------------- launch ----------------
extern "C" void kernel_launch(void* const* d_in, const int* in_sizes, int n_in,
                              void* d_out, int out_size) {
    const float* x   = (const float*)d_in[0];
    const int*   ei  = (const int*)d_in[1];   // edge_index is int32
    const float* W1  = (const float*)d_in[2];
    const float* b1  = (const float*)d_in[3];
    const float* W2  = (const float*)d_in[4];
    const float* b2  = (const float*)d_in[5];

    const int E = in_sizes[1] / 2;
    const int* srcp = ei;
    const int* dstp = ei + E;

    float* out = (float*)d_out;
    float* out_lsm = out;
    float* out_logit = nullptr;
    if (out_size >= 2 * N_NODES * NCLS) {
        out_logit = out + (size_t)N_NODES * NCLS;
    }

    const int T = 256;
    const int nodeBlocks = (N_NODES + T - 1) / T;
    const int edgeBlocks = (E + T - 1) / T;

    // CSR build
    k_zero      <<<nodeBlocks, T>>>();
    k_count     <<<edgeBlocks, T>>>(dstp, E);
    k_dinv      <<<nodeBlocks, T>>>();
    k_scan_local<<<SCAN_NB, 256>>>();
    k_scan_bsum <<<1, 512>>>();
    k_scan_add  <<<SCAN_NB, 256>>>();
    k_fill      <<<edgeBlocks, T>>>(srcp, dstp, E);

    // layer 1
    k_gemm1<<<(N_NODES + BM - 1) / BM, 256>>>(x, W1);
    long long w1 = (long long)N_NODES * 16;
    k_agg1<<<(int)((w1 + T - 1) / T), T>>>(w1);

    // layer 2
    k_gemm2<<<nodeBlocks, T>>>(W2, b1);
    long long w2 = (long long)N_NODES * 10;
    k_agg2<<<(int)((w2 + T - 1) / T), T>>>(w2);

    k_final<<<nodeBlocks, T>>>(b2, out_lsm, out_logit);
}